// round 5
// baseline (speedup 1.0000x reference)
#include <cuda_runtime.h>
#include <cstdint>

#define NN 50000
#define NE 1600000

// Scratch (static device globals — no allocation in kernel_launch)
__device__ float g_P[NN * 64];     // P[n][j] = fR_b1[j] + sum_k x[n][k] * fR_W1[k][j]      (dst part)
__device__ float g_Q[NN * 64];     // Q[n][j] =            sum_k x[n][k] * fR_W1[16+k][j]   (src part)
__device__ float g_agg[NN * 16];   // scatter-sum of e_new by dst

// ---------------------------------------------------------------------------
// K0: zero the aggregation buffer
// ---------------------------------------------------------------------------
__global__ void zero_agg_kernel() {
    int i = blockIdx.x * 256 + threadIdx.x;
    if (i < NN * 16 / 4) ((float4*)g_agg)[i] = make_float4(0.f, 0.f, 0.f, 0.f);
}

// ---------------------------------------------------------------------------
// K1: per-node precompute  P = x@W1[0:16] + b1,  Q = x@W1[16:32]
// ---------------------------------------------------------------------------
__global__ void __launch_bounds__(256) precompute_pq(
    const float* __restrict__ x, const float* __restrict__ W1,
    const float* __restrict__ b1)
{
    int idx = blockIdx.x * 256 + threadIdx.x;       // exactly NN*64 threads
    int n = idx >> 6, j = idx & 63;
    float p = b1[j], q = 0.f;
#pragma unroll
    for (int k = 0; k < 16; k++) {
        float xv = __ldg(x + n * 16 + k);           // broadcast within warp
        p = fmaf(xv, W1[k * 64 + j], p);
        q = fmaf(xv, W1[(16 + k) * 64 + j], q);
    }
    g_P[idx] = p;
    g_Q[idx] = q;
}

// ---------------------------------------------------------------------------
// K2: edge kernel. 64 edges/block, 128 threads = 32 edge-rows (2 edges each)
//     x 4 hidden col-groups (16 j each). Pure scalar fp32 — no inline PTX.
//   h[e][j]   = relu( P[dst_e][j] + Q[src_e][j] + sum_k e[e][k] * W1c[k][j] )
//   out[e][c] = b2[c] + sum_j h[e][j] * W2[j][c]
// ---------------------------------------------------------------------------
#define W2PAD 17   // row stride in floats: breaks the tx*16 bank-alias to 2-way max

__global__ void __launch_bounds__(128) edge_kernel(
    const int* __restrict__ ei, const float* __restrict__ e_in,
    const float* __restrict__ W1, const float* __restrict__ W2,
    const float* __restrict__ b2, float* __restrict__ e_out)
{
    __shared__ int s_src[64], s_dst[64];
    __shared__ __align__(16) float s_ET[16][64];      // e transposed [k][edge]
    __shared__ __align__(16) float s_W1[16][64];      // W1c rows (rows 32..47 of fR_W1)
    __shared__ __align__(16) float s_W2[64][W2PAD];   // W2 rows, padded
    __shared__ float s_b2[16];

    const int tid = threadIdx.x;
    const int tx = tid & 3;          // hidden col-group (16 j each)
    const int ty = tid >> 2;         // edge-row (2 edges each)
    const int base = blockIdx.x * 64;

    // ---- stage indices (edge_index is int32: JAX x64-disabled) ----
    if (tid < 64) {
        s_src[tid] = ei[base + tid];
        s_dst[tid] = ei[NE + base + tid];
    }
    // ---- stage e tile transposed to [k][edge]: 64 edges x 16 = 256 float4 ----
#pragma unroll
    for (int r = 0; r < 2; r++) {
        int idx = r * 128 + tid;                     // 0..255
        float4 v = ((const float4*)e_in)[base * 4 + idx];
        int edge = idx >> 2, part = idx & 3;
        s_ET[part * 4 + 0][edge] = v.x;
        s_ET[part * 4 + 1][edge] = v.y;
        s_ET[part * 4 + 2][edge] = v.z;
        s_ET[part * 4 + 3][edge] = v.w;
    }
    // ---- stage W1c (rows 32..47 of fR_W1) ----
#pragma unroll
    for (int r = 0; r < 8; r++) {
        int t = r * 128 + tid;                       // 0..1023
        s_W1[t >> 6][t & 63] = W1[32 * 64 + t];
    }
    // ---- stage W2 (padded rows) + b2 ----
#pragma unroll
    for (int r = 0; r < 8; r++) {
        int t = r * 128 + tid;                       // 0..1023
        s_W2[t >> 4][t & 15] = W2[t];
    }
    if (tid < 16) s_b2[tid] = b2[tid];
    __syncthreads();

    const int e0 = ty * 2, e1 = ty * 2 + 1;

    // ---- acc init: P[dst] + Q[src] on this thread's 16-j slice ----
    float acc[2][16];
#pragma unroll
    for (int p = 0; p < 2; p++) {
        int es = (p == 0) ? e0 : e1;
        const float4* Pp = (const float4*)(g_P + s_dst[es] * 64) + tx * 4;
        const float4* Qp = (const float4*)(g_Q + s_src[es] * 64) + tx * 4;
#pragma unroll
        for (int q = 0; q < 4; q++) {
            float4 pv = Pp[q];
            float4 qv = Qp[q];
            acc[p][q * 4 + 0] = pv.x + qv.x;
            acc[p][q * 4 + 1] = pv.y + qv.y;
            acc[p][q * 4 + 2] = pv.z + qv.z;
            acc[p][q * 4 + 3] = pv.w + qv.w;
        }
    }

    // ---- GEMM1: += e @ W1c  (16 k-steps x 2 edges x 16 j = 512 FMA) ----
#pragma unroll
    for (int k = 0; k < 16; k++) {
        float a0 = s_ET[k][e0];
        float a1 = s_ET[k][e1];
        const float4* wr = (const float4*)&s_W1[k][tx * 16];
#pragma unroll
        for (int q = 0; q < 4; q++) {
            float4 w = wr[q];
            acc[0][q * 4 + 0] = fmaf(a0, w.x, acc[0][q * 4 + 0]);
            acc[0][q * 4 + 1] = fmaf(a0, w.y, acc[0][q * 4 + 1]);
            acc[0][q * 4 + 2] = fmaf(a0, w.z, acc[0][q * 4 + 2]);
            acc[0][q * 4 + 3] = fmaf(a0, w.w, acc[0][q * 4 + 3]);
            acc[1][q * 4 + 0] = fmaf(a1, w.x, acc[1][q * 4 + 0]);
            acc[1][q * 4 + 1] = fmaf(a1, w.y, acc[1][q * 4 + 1]);
            acc[1][q * 4 + 2] = fmaf(a1, w.z, acc[1][q * 4 + 2]);
            acc[1][q * 4 + 3] = fmaf(a1, w.w, acc[1][q * 4 + 3]);
        }
    }

    // ---- ReLU ----
#pragma unroll
    for (int p = 0; p < 2; p++)
#pragma unroll
        for (int jj = 0; jj < 16; jj++)
            acc[p][jj] = fmaxf(acc[p][jj], 0.f);

    // ---- GEMM2 partials: this thread's 16 j contribute to all 16 c ----
    float oacc[2][16];
#pragma unroll
    for (int p = 0; p < 2; p++)
#pragma unroll
        for (int c = 0; c < 16; c++) oacc[p][c] = 0.f;

#pragma unroll
    for (int jj = 0; jj < 16; jj++) {
        int j = tx * 16 + jj;
        float h0 = acc[0][jj];
        float h1 = acc[1][jj];
        const float* wr = &s_W2[j][0];
#pragma unroll
        for (int c = 0; c < 16; c++) {
            float w = wr[c];
            oacc[0][c] = fmaf(h0, w, oacc[0][c]);
            oacc[1][c] = fmaf(h1, w, oacc[1][c]);
        }
    }

    // ---- reduce partial j-sums across the 4 tx lanes (butterfly xor 1, 2) ----
#pragma unroll
    for (int p = 0; p < 2; p++)
#pragma unroll
        for (int c = 0; c < 16; c++) {
            float v = oacc[p][c];
            v += __shfl_xor_sync(0xffffffffu, v, 1);
            v += __shfl_xor_sync(0xffffffffu, v, 2);
            oacc[p][c] = v;
        }

    // ---- epilogue: +b2, write e_new (float4 per lane), scatter scalar atomics ----
#pragma unroll
    for (int p = 0; p < 2; p++) {
        int eslot = (p == 0) ? e0 : e1;
        int edge = base + eslot;
        float4 ov;
        ov.x = oacc[p][tx * 4 + 0] + s_b2[tx * 4 + 0];
        ov.y = oacc[p][tx * 4 + 1] + s_b2[tx * 4 + 1];
        ov.z = oacc[p][tx * 4 + 2] + s_b2[tx * 4 + 2];
        ov.w = oacc[p][tx * 4 + 3] + s_b2[tx * 4 + 3];
        ((float4*)e_out)[edge * 4 + tx] = ov;
        float* ap = g_agg + s_dst[eslot] * 16 + tx * 4;
        atomicAdd(ap + 0, ov.x);
        atomicAdd(ap + 1, ov.y);
        atomicAdd(ap + 2, ov.z);
        atomicAdd(ap + 3, ov.w);
    }
}

// ---------------------------------------------------------------------------
// K3: node MLP  x_new = fO(concat(x, agg)). One node per thread; weights in smem.
// ---------------------------------------------------------------------------
__global__ void __launch_bounds__(256) node_kernel(
    const float* __restrict__ x,
    const float* __restrict__ W1, const float* __restrict__ b1,
    const float* __restrict__ W2, const float* __restrict__ b2,
    float* __restrict__ x_out)
{
    __shared__ float sW1[32 * 64];
    __shared__ float sW2[64 * 16];
    __shared__ float sb1[64];
    __shared__ float sb2[16];
    int tid = threadIdx.x;
#pragma unroll
    for (int r = 0; r < 8; r++) sW1[r * 256 + tid] = W1[r * 256 + tid];
#pragma unroll
    for (int r = 0; r < 4; r++) sW2[r * 256 + tid] = W2[r * 256 + tid];
    if (tid < 64) sb1[tid] = b1[tid];
    if (tid < 16) sb2[tid] = b2[tid];
    __syncthreads();

    int n = blockIdx.x * 256 + tid;
    if (n >= NN) return;

    float in[32];
#pragma unroll
    for (int q = 0; q < 4; q++) {
        float4 v = ((const float4*)x)[n * 4 + q];
        in[q * 4 + 0] = v.x; in[q * 4 + 1] = v.y;
        in[q * 4 + 2] = v.z; in[q * 4 + 3] = v.w;
        float4 a = ((const float4*)g_agg)[n * 4 + q];
        in[16 + q * 4 + 0] = a.x; in[16 + q * 4 + 1] = a.y;
        in[16 + q * 4 + 2] = a.z; in[16 + q * 4 + 3] = a.w;
    }
    float o[16];
#pragma unroll
    for (int c = 0; c < 16; c++) o[c] = sb2[c];
    for (int j = 0; j < 64; j++) {                   // keep j-loop rolled (I-cache)
        float h = sb1[j];
#pragma unroll
        for (int k = 0; k < 32; k++) h = fmaf(in[k], sW1[k * 64 + j], h);
        h = fmaxf(h, 0.f);
#pragma unroll
        for (int c = 0; c < 16; c++) o[c] = fmaf(h, sW2[j * 16 + c], o[c]);
    }
#pragma unroll
    for (int q = 0; q < 4; q++)
        ((float4*)x_out)[n * 4 + q] =
            make_float4(o[q * 4 + 0], o[q * 4 + 1], o[q * 4 + 2], o[q * 4 + 3]);
}

// ---------------------------------------------------------------------------
extern "C" void kernel_launch(void* const* d_in, const int* in_sizes, int n_in,
                              void* d_out, int out_size)
{
    const float* x     = (const float*)d_in[0];
    const int*   ei    = (const int*)d_in[1];    // edge_index: int32 (JAX x64 disabled)
    const float* e     = (const float*)d_in[2];
    const float* fRW1  = (const float*)d_in[3];
    const float* fRb1  = (const float*)d_in[4];
    const float* fRW2  = (const float*)d_in[5];
    const float* fRb2  = (const float*)d_in[6];
    const float* fOW1  = (const float*)d_in[7];
    const float* fOb1  = (const float*)d_in[8];
    const float* fOW2  = (const float*)d_in[9];
    const float* fOb2  = (const float*)d_in[10];

    float* x_new = (float*)d_out;            // [NN, 16]
    float* e_new = x_new + NN * 16;          // [NE, 16]

    zero_agg_kernel<<<(NN * 16 / 4 + 255) / 256, 256>>>();
    precompute_pq<<<(NN * 64) / 256, 256>>>(x, fRW1, fRb1);
    edge_kernel<<<NE / 64, 128>>>(ei, e, fRW1, fRW2, fRb2, e_new);
    node_kernel<<<(NN + 255) / 256, 256>>>(x, fOW1, fOb1, fOW2, fOb2, x_new);
}